// round 1
// baseline (speedup 1.0000x reference)
#include <cuda_runtime.h>

#define EPSF 2e-5f

// ---------------- scratch (static device memory: allowed) ----------------
__device__ float  g_a1[4096*5400];   // (B,12,9,50) post relu(maxpool(lift))
__device__ float  g_a2[4096*2016];   // (B,24,7,12) post relu(maxpool(conv2))
__device__ float  g_a3[4096*720];    // (B,48,5,3)  post relu(maxpool(conv3))
__device__ float  g_a4[4096*288];    // (B,96,3)    post relu(maxpool(conv4))
__device__ double g_stats[360];      // s1:0(12) q1:12(12) s2:24(24) q2:48(24)
                                     // s3:72(48) q3:120(48) s4:168(96) q4:264(96)
__device__ float  g_Wc[6*288];
__device__ float  g_bc[6];

__global__ void k_zero() {
    int t = threadIdx.x;
    if (t < 360) g_stats[t] = 0.0;
}

// ---------------- Phase 1: lift_conv + maxpool + relu + stats ----------------
__global__ __launch_bounds__(128) void k_phase1(const float* __restrict__ x,
                                                const float* __restrict__ w1) {
    __shared__ float xs[600];    // [c*100 + t]
    __shared__ float ws[504];    // w1[co*42 + c*7 + j]
    __shared__ float ssum[12], ssq[12];
    int tid = threadIdx.x;
    int b = blockIdx.x;
    for (int i = tid; i < 504; i += 128) ws[i] = w1[i];
    if (tid < 12) { ssum[tid] = 0.f; ssq[tid] = 0.f; }
    for (int i = tid; i < 600; i += 128) {
        int t = i / 6, c = i % 6;
        xs[c*100 + t] = x[b*600 + i];
    }
    __syncthreads();
    for (int o = tid; o < 5400; o += 128) {
        int co = o / 450;
        int rem = o % 450;
        int hh = rem / 50;
        int ox = rem % 50;
        int s = 1 << hh;
        int px = 2*ox;
        float a0 = 0.f, a1 = 0.f;
        const float* wr = &ws[co*42];
        #pragma unroll
        for (int c = 0; c < 6; c++) {
            const float* xc = &xs[c*100];
            #pragma unroll
            for (int j = 0; j < 7; j++) {
                float w = wr[c*7 + j];
                int t0 = px + (j-3)*s;
                if (t0 >= 0 && t0 < 100) a0 += xc[t0]*w;
                int t1 = t0 + 1;
                if (t1 >= 0 && t1 < 100) a1 += xc[t1]*w;
            }
        }
        float v = fmaxf(fmaxf(a0, a1), 0.f) * (1.f/(float)s);
        g_a1[b*5400 + o] = v;
        atomicAdd(&ssum[co], v);
        atomicAdd(&ssq[co], v*v);
    }
    __syncthreads();
    if (tid < 12) {
        atomicAdd(&g_stats[tid],    (double)ssum[tid]);
        atomicAdd(&g_stats[12+tid], (double)ssq[tid]);
    }
}

// ---------------- Phase 2: bn1 affine + pool + gg_conv(w2) + pool + relu + stats ----------------
__global__ __launch_bounds__(128) void k_phase2(const float* __restrict__ w2,
                                                const float* __restrict__ g1,
                                                const float* __restrict__ b1) {
    __shared__ float A[12], Bb[12];
    __shared__ float h2s[2700];   // (12,9,25)
    __shared__ float ws2[4320];   // (24,12,3,5)
    __shared__ float ssum[24], ssq[24];
    int tid = threadIdx.x;
    if (tid < 12) {
        double m = g_stats[tid] / 1843200.0;
        double v = g_stats[12+tid] / 1843200.0 - m*m;
        float a = g1[tid] * rsqrtf((float)v + EPSF);
        A[tid] = a;
        Bb[tid] = b1[tid] - (float)m * a;
    }
    if (tid < 24) { ssum[tid] = 0.f; ssq[tid] = 0.f; }
    for (int i = tid; i < 4320; i += 128) ws2[i] = w2[i];
    __syncthreads();
    for (int b = blockIdx.x; b < 4096; b += gridDim.x) {
        for (int i = tid; i < 2700; i += 128) {
            int c = i / 225;
            int rem = i % 225;
            int hh = rem / 25;
            int ox = rem % 25;
            const float* p = &g_a1[b*5400 + c*450 + hh*50 + 2*ox];
            float aa = A[c], bb = Bb[c];
            h2s[i] = fmaxf(aa*p[0]+bb, aa*p[1]+bb);
        }
        __syncthreads();
        for (int task = tid; task < 504; task += 128) {
            int cog = task / 84;
            int rem = task % 84;
            int ii = rem / 12;
            int ox = rem % 12;
            int s = 1 << ii;
            int px = 2*ox;
            float acc00=0,acc01=0,acc10=0,acc11=0,acc20=0,acc21=0,acc30=0,acc31=0;
            const float* wbase = &ws2[cog*4*180];
            for (int c = 0; c < 12; c++) {
                #pragma unroll
                for (int r = 0; r < 3; r++) {
                    const float* hp = &h2s[(c*9 + ii + r)*25];
                    const float* wp = &wbase[c*15 + r*5];
                    #pragma unroll
                    for (int j = 0; j < 5; j++) {
                        int t0 = px + (j-2)*s;
                        float a0 = (t0 >= 0 && t0 < 25) ? hp[t0] : 0.f;
                        int t1 = t0 + 1;
                        float a1 = (t1 >= 0 && t1 < 25) ? hp[t1] : 0.f;
                        float w0 = wp[j];
                        float w1_ = wp[180+j];
                        float w2_ = wp[360+j];
                        float w3_ = wp[540+j];
                        acc00 += w0*a0;  acc01 += w0*a1;
                        acc10 += w1_*a0; acc11 += w1_*a1;
                        acc20 += w2_*a0; acc21 += w2_*a1;
                        acc30 += w3_*a0; acc31 += w3_*a1;
                    }
                }
            }
            float inv = 1.f/(float)s;
            float vals[4] = {
                fmaxf(fmaxf(acc00,acc01),0.f)*inv,
                fmaxf(fmaxf(acc10,acc11),0.f)*inv,
                fmaxf(fmaxf(acc20,acc21),0.f)*inv,
                fmaxf(fmaxf(acc30,acc31),0.f)*inv };
            #pragma unroll
            for (int u = 0; u < 4; u++) {
                int co = cog*4 + u;
                float v = vals[u];
                g_a2[b*2016 + co*84 + ii*12 + ox] = v;
                atomicAdd(&ssum[co], v);
                atomicAdd(&ssq[co], v*v);
            }
        }
        __syncthreads();
    }
    if (tid < 24) {
        atomicAdd(&g_stats[24+tid], (double)ssum[tid]);
        atomicAdd(&g_stats[48+tid], (double)ssq[tid]);
    }
}

// ---------------- Phase 3: bn2 affine + pool + gg_conv(w3) + pool + relu + stats ----------------
__global__ __launch_bounds__(128) void k_phase3(const float* __restrict__ w3,
                                                const float* __restrict__ g2,
                                                const float* __restrict__ b2) {
    extern __shared__ float sm3[];
    float* ws3  = sm3;            // 17280
    float* h3s  = sm3 + 17280;    // 1008  (24,7,6)
    float* A    = h3s + 1008;     // 24
    float* Bb   = A + 24;         // 24
    float* ssum = Bb + 24;        // 48
    float* ssq  = ssum + 48;      // 48
    int tid = threadIdx.x;
    if (tid < 24) {
        double m = g_stats[24+tid] / 344064.0;
        double v = g_stats[48+tid] / 344064.0 - m*m;
        float a = g2[tid] * rsqrtf((float)v + EPSF);
        A[tid] = a; Bb[tid] = b2[tid] - (float)m*a;
    }
    if (tid < 48) { ssum[tid] = 0.f; ssq[tid] = 0.f; }
    for (int i = tid; i < 17280; i += 128) ws3[i] = w3[i];
    __syncthreads();
    for (int b = blockIdx.x; b < 4096; b += gridDim.x) {
        for (int i = tid; i < 1008; i += 128) {
            int c = i / 42; int rem = i % 42; int hh = rem / 6; int ox = rem % 6;
            const float* p = &g_a2[b*2016 + c*84 + hh*12 + 2*ox];
            float aa = A[c], bb = Bb[c];
            h3s[i] = fmaxf(aa*p[0]+bb, aa*p[1]+bb);
        }
        __syncthreads();
        for (int task = tid; task < 180; task += 128) {
            int cog = task / 15;
            int rem = task % 15;
            int ii = rem / 3;
            int ox = rem % 3;
            int s = 1 << ii;
            int px = 2*ox;
            float acc00=0,acc01=0,acc10=0,acc11=0,acc20=0,acc21=0,acc30=0,acc31=0;
            const float* wbase = &ws3[cog*4*360];
            for (int c = 0; c < 24; c++) {
                #pragma unroll
                for (int r = 0; r < 3; r++) {
                    const float* hp = &h3s[(c*7 + ii + r)*6];
                    const float* wp = &wbase[c*15 + r*5];
                    #pragma unroll
                    for (int j = 0; j < 5; j++) {
                        int t0 = px + (j-2)*s;
                        float a0 = (t0 >= 0 && t0 < 6) ? hp[t0] : 0.f;
                        int t1 = t0 + 1;
                        float a1 = (t1 >= 0 && t1 < 6) ? hp[t1] : 0.f;
                        float w0 = wp[j];
                        float w1_ = wp[360+j];
                        float w2_ = wp[720+j];
                        float w3_ = wp[1080+j];
                        acc00 += w0*a0;  acc01 += w0*a1;
                        acc10 += w1_*a0; acc11 += w1_*a1;
                        acc20 += w2_*a0; acc21 += w2_*a1;
                        acc30 += w3_*a0; acc31 += w3_*a1;
                    }
                }
            }
            float inv = 1.f/(float)s;
            float vals[4] = {
                fmaxf(fmaxf(acc00,acc01),0.f)*inv,
                fmaxf(fmaxf(acc10,acc11),0.f)*inv,
                fmaxf(fmaxf(acc20,acc21),0.f)*inv,
                fmaxf(fmaxf(acc30,acc31),0.f)*inv };
            #pragma unroll
            for (int u = 0; u < 4; u++) {
                int co = cog*4 + u;
                float v = vals[u];
                g_a3[b*720 + co*15 + ii*3 + ox] = v;
                atomicAdd(&ssum[co], v);
                atomicAdd(&ssq[co], v*v);
            }
        }
        __syncthreads();
    }
    if (tid < 48) {
        atomicAdd(&g_stats[72+tid],  (double)ssum[tid]);
        atomicAdd(&g_stats[120+tid], (double)ssq[tid]);
    }
}

// ---------------- Phase 4: bn3 affine + gg_conv(w4) + pool + relu + stats ----------------
__global__ __launch_bounds__(256) void k_phase4(const float* __restrict__ w4,
                                                const float* __restrict__ g3,
                                                const float* __restrict__ b3) {
    extern __shared__ float sm4[];
    float* ws4  = sm4;            // 41472
    float* h4s  = ws4 + 41472;    // 720 (48,5,3)
    float* A    = h4s + 720;      // 48
    float* Bb   = A + 48;         // 48
    float* ssum = Bb + 48;        // 96
    float* ssq  = ssum + 96;      // 96
    int tid = threadIdx.x;
    if (tid < 48) {
        double m = g_stats[72+tid] / 61440.0;
        double v = g_stats[120+tid] / 61440.0 - m*m;
        float a = g3[tid] * rsqrtf((float)v + EPSF);
        A[tid] = a; Bb[tid] = b3[tid] - (float)m*a;
    }
    if (tid < 96) { ssum[tid] = 0.f; ssq[tid] = 0.f; }
    for (int i = tid; i < 41472; i += 256) ws4[i] = w4[i];
    __syncthreads();
    for (int b = blockIdx.x; b < 4096; b += gridDim.x) {
        for (int i = tid; i < 720; i += 256) {
            int c = i / 15;
            h4s[i] = A[c]*g_a3[b*720 + i] + Bb[c];
        }
        __syncthreads();
        for (int task = tid; task < 288; task += 256) {
            int co = task / 3;
            int ii = task % 3;
            int s = 1 << ii;
            float acc0 = 0.f, acc1 = 0.f;
            const float* wbase = &ws4[co*432];
            for (int c = 0; c < 48; c++) {
                #pragma unroll
                for (int r = 0; r < 3; r++) {
                    const float* hp = &h4s[(c*5 + ii + r)*3];
                    const float* wp = &wbase[c*9 + r*3];
                    #pragma unroll
                    for (int j = 0; j < 3; j++) {
                        int t0 = (j-1)*s;
                        float a0 = (t0 >= 0 && t0 < 3) ? hp[t0] : 0.f;
                        int t1 = t0 + 1;
                        float a1 = (t1 >= 0 && t1 < 3) ? hp[t1] : 0.f;
                        float w = wp[j];
                        acc0 += w*a0; acc1 += w*a1;
                    }
                }
            }
            float v = fmaxf(fmaxf(acc0, acc1), 0.f) * (1.f/(float)s);
            g_a4[b*288 + co*3 + ii] = v;
            atomicAdd(&ssum[co], v);
            atomicAdd(&ssq[co], v*v);
        }
        __syncthreads();
    }
    if (tid < 96) {
        atomicAdd(&g_stats[168+tid], (double)ssum[tid]);
        atomicAdd(&g_stats[264+tid], (double)ssq[tid]);
    }
}

// ---------------- Phase 5a: bn4 affine + collapse 3 FCs into (6x288) + bias ----------------
__global__ __launch_bounds__(256) void k_phase5a(const float* __restrict__ g4, const float* __restrict__ b4,
                                                 const float* __restrict__ f1w, const float* __restrict__ f1b,
                                                 const float* __restrict__ f2w, const float* __restrict__ f2b,
                                                 const float* __restrict__ f3w, const float* __restrict__ f3b) {
    __shared__ float A4[96], B4[96], W23[576], bcs[6];
    int tid = threadIdx.x;
    if (tid < 96) {
        double m = g_stats[168+tid] / 12288.0;
        double v = g_stats[264+tid] / 12288.0 - m*m;
        float a = g4[tid] * rsqrtf((float)v + EPSF);
        A4[tid] = a; B4[tid] = b4[tid] - (float)m*a;
    }
    if (tid < 6) bcs[tid] = 0.f;
    for (int idx = tid; idx < 576; idx += 256) {
        int j = idx / 96, k = idx % 96;
        float s = 0.f;
        for (int l = 0; l < 48; l++) s += f3w[j*48 + l] * f2w[l*96 + k];
        W23[idx] = s;
    }
    __syncthreads();
    for (int idx = tid; idx < 1728; idx += 256) {
        int j = idx / 288, i = idx % 288;
        int c = i / 3;
        float s0 = 0.f;
        for (int k = 0; k < 96; k++) s0 += W23[j*96 + k] * f1w[k*288 + i];
        g_Wc[idx] = s0 * A4[c];
        atomicAdd(&bcs[j], s0 * B4[c]);
    }
    __syncthreads();
    if (tid < 6) {
        int j = tid;
        float bb = f3b[j];
        for (int l = 0; l < 48; l++) bb += f3w[j*48 + l] * f2b[l];
        for (int k = 0; k < 96; k++) bb += W23[j*96 + k] * f1b[k];
        g_bc[j] = bcs[j] + bb;
    }
}

// ---------------- Phase 5b: out = a4 @ Wc^T + bc ----------------
__global__ __launch_bounds__(256) void k_phase5b(float* __restrict__ out) {
    int w = (blockIdx.x * blockDim.x + threadIdx.x) >> 5;
    int lane = threadIdx.x & 31;
    if (w >= 4096) return;
    const float* a = &g_a4[w*288];
    float acc[6] = {0.f,0.f,0.f,0.f,0.f,0.f};
    for (int i = lane; i < 288; i += 32) {
        float v = a[i];
        #pragma unroll
        for (int j = 0; j < 6; j++) acc[j] += v * g_Wc[j*288 + i];
    }
    #pragma unroll
    for (int j = 0; j < 6; j++)
        #pragma unroll
        for (int off = 16; off; off >>= 1)
            acc[j] += __shfl_down_sync(0xffffffffu, acc[j], off);
    if (lane == 0) {
        #pragma unroll
        for (int j = 0; j < 6; j++) out[w*6 + j] = acc[j] + g_bc[j];
    }
}

// ---------------- launcher ----------------
extern "C" void kernel_launch(void* const* d_in, const int* in_sizes, int n_in,
                              void* d_out, int out_size) {
    const float* x   = (const float*)d_in[0];
    const float* w1  = (const float*)d_in[1];
    const float* w2  = (const float*)d_in[2];
    const float* w3  = (const float*)d_in[3];
    const float* w4  = (const float*)d_in[4];
    const float* g1  = (const float*)d_in[5];
    const float* b1  = (const float*)d_in[6];
    const float* g2  = (const float*)d_in[7];
    const float* b2  = (const float*)d_in[8];
    const float* g3  = (const float*)d_in[9];
    const float* b3  = (const float*)d_in[10];
    const float* g4  = (const float*)d_in[11];
    const float* b4  = (const float*)d_in[12];
    const float* f1w = (const float*)d_in[13];
    const float* f1b = (const float*)d_in[14];
    const float* f2w = (const float*)d_in[15];
    const float* f2b = (const float*)d_in[16];
    const float* f3w = (const float*)d_in[17];
    const float* f3b = (const float*)d_in[18];
    float* out = (float*)d_out;

    cudaFuncSetAttribute(k_phase3, cudaFuncAttributeMaxDynamicSharedMemorySize, 18432*4);
    cudaFuncSetAttribute(k_phase4, cudaFuncAttributeMaxDynamicSharedMemorySize, 42480*4);

    k_zero<<<1, 384>>>();
    k_phase1<<<4096, 128>>>(x, w1);
    k_phase2<<<512, 128>>>(w2, g1, b1);
    k_phase3<<<512, 128, 18432*4>>>(w3, g2, b2);
    k_phase4<<<152, 256, 42480*4>>>(w4, g3, b3);
    k_phase5a<<<1, 256>>>(g4, b4, f1w, f1b, f2w, f2b, f3w, f3b);
    k_phase5b<<<512, 256>>>(out);
}

// round 2
// speedup vs baseline: 1.4711x; 1.4711x over previous
#include <cuda_runtime.h>

#define EPSF 2e-5f

// ---------------- scratch (static device memory: allowed) ----------------
__device__ float  g_a1[4096*5400];   // (B,12,9,50) post relu(maxpool(lift))
__device__ float  g_a2[4096*2016];   // (B,24,7,12) post relu(maxpool(conv2))
__device__ float  g_a3[4096*720];    // (B,48,5,3)  post relu(maxpool(conv3))
__device__ float  g_a4[4096*288];    // (B,96,3)    post relu(maxpool(conv4))
__device__ double g_stats[360];      // s1:0(12) q1:12(12) s2:24(24) q2:48(24)
                                     // s3:72(48) q3:120(48) s4:168(96) q4:264(96)
__device__ float  g_Wc[6*288];
__device__ float  g_bc[6];

__global__ void k_zero() {
    int t = threadIdx.x;
    if (t < 360) g_stats[t] = 0.0;
}

// ---------------- Phase 1: lift_conv + maxpool + relu + stats ----------------
// 2 samples/block, 256 threads, co-tile = 12 (all), weights transposed [k][co].
__global__ __launch_bounds__(256) void k_phase1(const float* __restrict__ x,
                                                const float* __restrict__ w1) {
    __shared__ float xs[2*600];      // [s][c*100 + t]
    __shared__ float wst[504];       // [(c*7+j)*12 + co]
    __shared__ float ssum[12], ssq[12];
    int tid = threadIdx.x;
    int b0 = blockIdx.x * 2;
    for (int i = tid; i < 504; i += 256) {
        int co = i / 42, rem = i % 42;
        wst[rem*12 + co] = w1[i];
    }
    if (tid < 12) { ssum[tid] = 0.f; ssq[tid] = 0.f; }
    for (int i = tid; i < 1200; i += 256) {
        int s_l = i / 600, idx = i % 600;
        int t = idx / 6, c = idx % 6;
        xs[s_l*600 + c*100 + t] = x[(b0 + s_l)*600 + idx];
    }
    __syncthreads();
    for (int task = tid; task < 900; task += 256) {
        int s_l = task / 450;
        int rem = task % 450;
        int hh = rem / 50;
        int ox = rem % 50;
        int sc = 1 << hh;
        int px = 2*ox;
        float acc0[12], acc1[12];
        #pragma unroll
        for (int u = 0; u < 12; u++) { acc0[u] = 0.f; acc1[u] = 0.f; }
        const float* xb = &xs[s_l*600];
        #pragma unroll
        for (int c = 0; c < 6; c++) {
            const float* xc = xb + c*100;
            #pragma unroll
            for (int j = 0; j < 7; j++) {
                int t0 = px + (j-3)*sc;
                float a0 = (t0 >= 0 && t0 < 100) ? xc[t0]   : 0.f;
                float a1 = (t0 >= -1 && t0 < 99) ? xc[t0+1] : 0.f;
                const float* wr = &wst[(c*7 + j)*12];
                #pragma unroll
                for (int u = 0; u < 12; u++) {
                    float w = wr[u];
                    acc0[u] += w*a0;
                    acc1[u] += w*a1;
                }
            }
        }
        float inv = 1.f/(float)sc;
        int b = b0 + s_l;
        #pragma unroll
        for (int u = 0; u < 12; u++) {
            float v = fmaxf(fmaxf(acc0[u], acc1[u]), 0.f) * inv;
            g_a1[b*5400 + u*450 + hh*50 + ox] = v;
            atomicAdd(&ssum[u], v);
            atomicAdd(&ssq[u], v*v);
        }
    }
    __syncthreads();
    if (tid < 12) {
        atomicAdd(&g_stats[tid],    (double)ssum[tid]);
        atomicAdd(&g_stats[12+tid], (double)ssq[tid]);
    }
}

// ---------------- Phase 2: bn1 + pool + gg_conv(w2) + pool + relu + stats ----------------
// 4 samples/block, 256 threads, co-tile = 8, dyn smem.
__global__ __launch_bounds__(256) void k_phase2(const float* __restrict__ w2,
                                                const float* __restrict__ g1,
                                                const float* __restrict__ b1) {
    extern __shared__ float sm2[];
    float* ws2t = sm2;            // 4320  [( (c*3+r)*5+j )*24 + co]
    float* acts = sm2 + 4320;     // 4*2700 [s][ (c*9+hh)*25 + x ]
    float* A    = acts + 10800;   // 12
    float* Bb   = A + 12;         // 12
    float* ssum = Bb + 12;        // 24
    float* ssq  = ssum + 24;      // 24
    int tid = threadIdx.x;
    int b0 = blockIdx.x * 4;
    if (tid < 12) {
        double m = g_stats[tid] / 1843200.0;
        double v = g_stats[12+tid] / 1843200.0 - m*m;
        float a = g1[tid] * rsqrtf((float)v + EPSF);
        A[tid] = a;
        Bb[tid] = b1[tid] - (float)m * a;
    }
    if (tid < 24) { ssum[tid] = 0.f; ssq[tid] = 0.f; }
    for (int i = tid; i < 4320; i += 256) {
        int co = i / 180, rem = i % 180;
        ws2t[rem*24 + co] = w2[i];
    }
    __syncthreads();
    for (int i = tid; i < 10800; i += 256) {
        int s_l = i / 2700, rem = i % 2700;
        int c = rem / 225;
        int r2 = rem % 225;
        int hh = r2 / 25;
        int ox = r2 % 25;
        int b = b0 + s_l;
        float2 p = *reinterpret_cast<const float2*>(&g_a1[b*5400 + c*450 + hh*50 + 2*ox]);
        float aa = A[c], bb = Bb[c];
        acts[s_l*2700 + (c*9 + hh)*25 + ox] = fmaxf(aa*p.x + bb, aa*p.y + bb);
    }
    __syncthreads();
    // tasks: [cog(3)][s(4)][ii(7)][ox(12)] = 1008
    for (int task = tid; task < 1008; task += 256) {
        int cog = task / 336;
        int rem = task % 336;
        int s_l = rem / 84;
        int r2  = rem % 84;
        int ii  = r2 / 12;
        int ox  = r2 % 12;
        int sc = 1 << ii;
        int px = 2*ox;
        int co0 = cog*8;
        float acc0[8], acc1[8];
        #pragma unroll
        for (int u = 0; u < 8; u++) { acc0[u] = 0.f; acc1[u] = 0.f; }
        const float* ab = &acts[s_l*2700];
        for (int c = 0; c < 12; c++) {
            #pragma unroll
            for (int r = 0; r < 3; r++) {
                const float* hp = ab + (c*9 + ii + r)*25;
                const float* wr = &ws2t[((c*3 + r)*5)*24 + co0];
                #pragma unroll
                for (int j = 0; j < 5; j++) {
                    int t0 = px + (j-2)*sc;
                    float a0 = (t0 >= 0 && t0 < 25) ? hp[t0]   : 0.f;
                    float a1 = (t0 >= -1 && t0 < 24) ? hp[t0+1] : 0.f;
                    const float* wj = wr + j*24;
                    #pragma unroll
                    for (int u = 0; u < 8; u++) {
                        float w = wj[u];
                        acc0[u] += w*a0;
                        acc1[u] += w*a1;
                    }
                }
            }
        }
        float inv = 1.f/(float)sc;
        int b = b0 + s_l;
        #pragma unroll
        for (int u = 0; u < 8; u++) {
            float v = fmaxf(fmaxf(acc0[u], acc1[u]), 0.f)*inv;
            int co = co0 + u;
            g_a2[b*2016 + co*84 + ii*12 + ox] = v;
            atomicAdd(&ssum[co], v);
            atomicAdd(&ssq[co], v*v);
        }
    }
    __syncthreads();
    if (tid < 24) {
        atomicAdd(&g_stats[24+tid], (double)ssum[tid]);
        atomicAdd(&g_stats[48+tid], (double)ssq[tid]);
    }
}

// ---------------- Phase 3: bn2 + pool + gg_conv(w3) + pool + relu + stats ----------------
// 8 samples/block, 256 threads, co-tile = 8, dyn smem.
__global__ __launch_bounds__(256) void k_phase3(const float* __restrict__ w3,
                                                const float* __restrict__ g2,
                                                const float* __restrict__ b2) {
    extern __shared__ float sm3[];
    float* ws3t = sm3;            // 17280 [( (c*3+r)*5+j )*48 + co]
    float* acts = sm3 + 17280;    // 8*1008 [s][ (c*7+hh)*6 + x ]
    float* A    = acts + 8064;    // 24
    float* Bb   = A + 24;         // 24
    float* ssum = Bb + 24;        // 48
    float* ssq  = ssum + 48;      // 48
    int tid = threadIdx.x;
    int b0 = blockIdx.x * 8;
    if (tid < 24) {
        double m = g_stats[24+tid] / 344064.0;
        double v = g_stats[48+tid] / 344064.0 - m*m;
        float a = g2[tid] * rsqrtf((float)v + EPSF);
        A[tid] = a; Bb[tid] = b2[tid] - (float)m*a;
    }
    if (tid < 48) { ssum[tid] = 0.f; ssq[tid] = 0.f; }
    for (int i = tid; i < 17280; i += 256) {
        int co = i / 360, rem = i % 360;
        ws3t[rem*48 + co] = w3[i];
    }
    __syncthreads();
    for (int i = tid; i < 8064; i += 256) {
        int s_l = i / 1008, rem = i % 1008;
        int c = rem / 42;
        int r2 = rem % 42;
        int hh = r2 / 6;
        int ox = r2 % 6;
        int b = b0 + s_l;
        float2 p = *reinterpret_cast<const float2*>(&g_a2[b*2016 + c*84 + hh*12 + 2*ox]);
        float aa = A[c], bb = Bb[c];
        acts[s_l*1008 + (c*7 + hh)*6 + ox] = fmaxf(aa*p.x + bb, aa*p.y + bb);
    }
    __syncthreads();
    // tasks: [cog(6)][s(8)][ii(5)][ox(3)] = 720
    for (int task = tid; task < 720; task += 256) {
        int cog = task / 120;
        int rem = task % 120;
        int s_l = rem / 15;
        int r2  = rem % 15;
        int ii  = r2 / 3;
        int ox  = r2 % 3;
        int sc = 1 << ii;
        int px = 2*ox;
        int co0 = cog*8;
        float acc0[8], acc1[8];
        #pragma unroll
        for (int u = 0; u < 8; u++) { acc0[u] = 0.f; acc1[u] = 0.f; }
        const float* ab = &acts[s_l*1008];
        for (int c = 0; c < 24; c++) {
            #pragma unroll
            for (int r = 0; r < 3; r++) {
                const float* hp = ab + (c*7 + ii + r)*6;
                const float* wr = &ws3t[((c*3 + r)*5)*48 + co0];
                #pragma unroll
                for (int j = 0; j < 5; j++) {
                    int t0 = px + (j-2)*sc;
                    float a0 = (t0 >= 0 && t0 < 6) ? hp[t0]   : 0.f;
                    float a1 = (t0 >= -1 && t0 < 5) ? hp[t0+1] : 0.f;
                    const float* wj = wr + j*48;
                    #pragma unroll
                    for (int u = 0; u < 8; u++) {
                        float w = wj[u];
                        acc0[u] += w*a0;
                        acc1[u] += w*a1;
                    }
                }
            }
        }
        float inv = 1.f/(float)sc;
        int b = b0 + s_l;
        #pragma unroll
        for (int u = 0; u < 8; u++) {
            float v = fmaxf(fmaxf(acc0[u], acc1[u]), 0.f)*inv;
            int co = co0 + u;
            g_a3[b*720 + co*15 + ii*3 + ox] = v;
            atomicAdd(&ssum[co], v);
            atomicAdd(&ssq[co], v*v);
        }
    }
    __syncthreads();
    if (tid < 48) {
        atomicAdd(&g_stats[72+tid],  (double)ssum[tid]);
        atomicAdd(&g_stats[120+tid], (double)ssq[tid]);
    }
}

// ---------------- Phase 4: bn3 + gg_conv(w4) + pool + relu + stats ----------------
// 12 samples/block, 512 threads, co-tile = 8, full transposed weights in dyn smem.
__global__ __launch_bounds__(512) void k_phase4(const float* __restrict__ w4,
                                                const float* __restrict__ g3,
                                                const float* __restrict__ b3) {
    extern __shared__ float sm4[];
    float* ws4t = sm4;            // 41472 [( (c*3+r)*3+j )*96 + co]
    float* acts = sm4 + 41472;    // 12*720 [s][ (c*5+hh)*3 + x ]
    float* A    = acts + 8640;    // 48
    float* Bb   = A + 48;         // 48
    float* ssum = Bb + 48;        // 96
    float* ssq  = ssum + 96;      // 96
    int tid = threadIdx.x;
    int b0 = blockIdx.x * 12;
    int nS = 4096 - b0; if (nS > 12) nS = 12;
    if (tid < 48) {
        double m = g_stats[72+tid] / 61440.0;
        double v = g_stats[120+tid] / 61440.0 - m*m;
        float a = g3[tid] * rsqrtf((float)v + EPSF);
        A[tid] = a; Bb[tid] = b3[tid] - (float)m*a;
    }
    if (tid < 96) { ssum[tid] = 0.f; ssq[tid] = 0.f; }
    for (int i = tid; i < 41472; i += 512) {
        int co = i / 432, rem = i % 432;
        ws4t[rem*96 + co] = w4[i];
    }
    __syncthreads();
    for (int i = tid; i < nS*720; i += 512) {
        int s_l = i / 720, rem = i % 720;
        int c = rem / 15;
        acts[s_l*720 + rem] = A[c]*g_a3[(b0+s_l)*720 + rem] + Bb[c];
    }
    __syncthreads();
    // tasks: [cog(12)][s(12)][ii(3)] = 432
    for (int task = tid; task < 432; task += 512) {
        int cog = task / 36;
        int rem = task % 36;
        int s_l = rem / 3;
        int ii  = rem % 3;
        if (s_l >= nS) continue;
        int sc = 1 << ii;
        int co0 = cog*8;
        float acc0[8], acc1[8];
        #pragma unroll
        for (int u = 0; u < 8; u++) { acc0[u] = 0.f; acc1[u] = 0.f; }
        const float* ab = &acts[s_l*720];
        for (int c = 0; c < 48; c++) {
            #pragma unroll
            for (int r = 0; r < 3; r++) {
                const float* hp = ab + (c*5 + ii + r)*3;
                const float* wr = &ws4t[((c*3 + r)*3)*96 + co0];
                #pragma unroll
                for (int j = 0; j < 3; j++) {
                    int t0 = (j-1)*sc;
                    float a0 = (t0 >= 0 && t0 < 3) ? hp[t0]   : 0.f;
                    float a1 = (t0 >= -1 && t0 < 2) ? hp[t0+1] : 0.f;
                    const float* wj = wr + j*96;
                    #pragma unroll
                    for (int u = 0; u < 8; u++) {
                        float w = wj[u];
                        acc0[u] += w*a0;
                        acc1[u] += w*a1;
                    }
                }
            }
        }
        float inv = 1.f/(float)sc;
        int b = b0 + s_l;
        #pragma unroll
        for (int u = 0; u < 8; u++) {
            float v = fmaxf(fmaxf(acc0[u], acc1[u]), 0.f)*inv;
            int co = co0 + u;
            g_a4[b*288 + co*3 + ii] = v;
            atomicAdd(&ssum[co], v);
            atomicAdd(&ssq[co], v*v);
        }
    }
    __syncthreads();
    if (tid < 96) {
        atomicAdd(&g_stats[168+tid], (double)ssum[tid]);
        atomicAdd(&g_stats[264+tid], (double)ssq[tid]);
    }
}

// ---------------- Phase 5a: bn4 affine + collapse 3 FCs into (6x288) + bias ----------------
__global__ __launch_bounds__(256) void k_phase5a(const float* __restrict__ g4, const float* __restrict__ b4,
                                                 const float* __restrict__ f1w, const float* __restrict__ f1b,
                                                 const float* __restrict__ f2w, const float* __restrict__ f2b,
                                                 const float* __restrict__ f3w, const float* __restrict__ f3b) {
    __shared__ float A4[96], B4[96], W23[576], bcs[6];
    int tid = threadIdx.x;
    if (tid < 96) {
        double m = g_stats[168+tid] / 12288.0;
        double v = g_stats[264+tid] / 12288.0 - m*m;
        float a = g4[tid] * rsqrtf((float)v + EPSF);
        A4[tid] = a; B4[tid] = b4[tid] - (float)m*a;
    }
    if (tid < 6) bcs[tid] = 0.f;
    for (int idx = tid; idx < 576; idx += 256) {
        int j = idx / 96, k = idx % 96;
        float s = 0.f;
        for (int l = 0; l < 48; l++) s += f3w[j*48 + l] * f2w[l*96 + k];
        W23[idx] = s;
    }
    __syncthreads();
    for (int idx = tid; idx < 1728; idx += 256) {
        int j = idx / 288, i = idx % 288;
        int c = i / 3;
        float s0 = 0.f;
        for (int k = 0; k < 96; k++) s0 += W23[j*96 + k] * f1w[k*288 + i];
        g_Wc[idx] = s0 * A4[c];
        atomicAdd(&bcs[j], s0 * B4[c]);
    }
    __syncthreads();
    if (tid < 6) {
        int j = tid;
        float bb = f3b[j];
        for (int l = 0; l < 48; l++) bb += f3w[j*48 + l] * f2b[l];
        for (int k = 0; k < 96; k++) bb += W23[j*96 + k] * f1b[k];
        g_bc[j] = bcs[j] + bb;
    }
}

// ---------------- Phase 5b: out = a4 @ Wc^T + bc ----------------
__global__ __launch_bounds__(256) void k_phase5b(float* __restrict__ out) {
    int w = (blockIdx.x * blockDim.x + threadIdx.x) >> 5;
    int lane = threadIdx.x & 31;
    if (w >= 4096) return;
    const float* a = &g_a4[w*288];
    float acc[6] = {0.f,0.f,0.f,0.f,0.f,0.f};
    for (int i = lane; i < 288; i += 32) {
        float v = a[i];
        #pragma unroll
        for (int j = 0; j < 6; j++) acc[j] += v * g_Wc[j*288 + i];
    }
    #pragma unroll
    for (int j = 0; j < 6; j++)
        #pragma unroll
        for (int off = 16; off; off >>= 1)
            acc[j] += __shfl_down_sync(0xffffffffu, acc[j], off);
    if (lane == 0) {
        #pragma unroll
        for (int j = 0; j < 6; j++) out[w*6 + j] = acc[j] + g_bc[j];
    }
}

// ---------------- launcher ----------------
extern "C" void kernel_launch(void* const* d_in, const int* in_sizes, int n_in,
                              void* d_out, int out_size) {
    const float* x   = (const float*)d_in[0];
    const float* w1  = (const float*)d_in[1];
    const float* w2  = (const float*)d_in[2];
    const float* w3  = (const float*)d_in[3];
    const float* w4  = (const float*)d_in[4];
    const float* g1  = (const float*)d_in[5];
    const float* b1  = (const float*)d_in[6];
    const float* g2  = (const float*)d_in[7];
    const float* b2  = (const float*)d_in[8];
    const float* g3  = (const float*)d_in[9];
    const float* b3  = (const float*)d_in[10];
    const float* g4  = (const float*)d_in[11];
    const float* b4  = (const float*)d_in[12];
    const float* f1w = (const float*)d_in[13];
    const float* f1b = (const float*)d_in[14];
    const float* f2w = (const float*)d_in[15];
    const float* f2b = (const float*)d_in[16];
    const float* f3w = (const float*)d_in[17];
    const float* f3b = (const float*)d_in[18];
    float* out = (float*)d_out;

    static const int SM2 = (4320 + 10800 + 12 + 12 + 24 + 24) * 4;
    static const int SM3 = (17280 + 8064 + 24 + 24 + 48 + 48) * 4;
    static const int SM4 = (41472 + 8640 + 48 + 48 + 96 + 96) * 4;
    cudaFuncSetAttribute(k_phase2, cudaFuncAttributeMaxDynamicSharedMemorySize, SM2);
    cudaFuncSetAttribute(k_phase3, cudaFuncAttributeMaxDynamicSharedMemorySize, SM3);
    cudaFuncSetAttribute(k_phase4, cudaFuncAttributeMaxDynamicSharedMemorySize, SM4);

    k_zero<<<1, 384>>>();
    k_phase1<<<2048, 256>>>(x, w1);
    k_phase2<<<1024, 256, SM2>>>(w2, g1, b1);
    k_phase3<<<512, 256, SM3>>>(w3, g2, b2);
    k_phase4<<<342, 512, SM4>>>(w4, g3, b3);
    k_phase5a<<<1, 256>>>(g4, b4, f1w, f1b, f2w, f2b, f3w, f3b);
    k_phase5b<<<512, 256>>>(out);
}

// round 3
// speedup vs baseline: 3.9290x; 2.6708x over previous
#include <cuda_runtime.h>

#define EPSF 2e-5f
#define NB 4096

// ---------------- scratch planes, [feature][batch] ----------------
__device__ float  g_xT [600*NB];    // x transposed: [(t*6+c)][b]
__device__ float  g_a1T[5400*NB];   // (12,9,50) relu(maxpool(lift))
__device__ float  g_p2 [2700*NB];   // bn1+pool: (12,9,25)
__device__ float  g_a2T[2016*NB];   // (24,7,12)
__device__ float  g_p3 [1008*NB];   // bn2+pool: (24,7,6)
__device__ float  g_a3T[720*NB];    // (48,5,3)
__device__ float  g_p4 [720*NB];    // bn3: (48,5,3)
__device__ float  g_a4T[288*NB];    // (96,3)
__device__ double g_stats[360];     // s1:0 q1:12 s2:24 q2:48 s3:72 q3:120 s4:168 q4:264
__device__ float  g_Wc[6*288];
__device__ float  g_bc[6];

__global__ void k_zero() {
    int t = threadIdx.x;
    if (t < 360) g_stats[t] = 0.0;
}

// ---------------- transpose x (4096,600) -> xT (600,4096) ----------------
__global__ void k_tr(const float* __restrict__ x) {
    __shared__ float tile[32][33];
    int bx = blockIdx.x * 32;
    int fy = blockIdx.y * 32;
    int tx = threadIdx.x, ty = threadIdx.y;
    #pragma unroll
    for (int m = 0; m < 4; m++) {
        int ff = fy + tx;
        tile[ty + m*8][tx] = (ff < 600) ? x[(bx + ty + m*8)*600 + ff] : 0.f;
    }
    __syncthreads();
    #pragma unroll
    for (int m = 0; m < 4; m++) {
        int ff = fy + ty + m*8;
        if (ff < 600) g_xT[ff*NB + bx + tx] = tile[tx][ty + m*8];
    }
}

// ---------------- Phase 1: lift conv, warp=32 samples, all 12 co in regs ----------------
__global__ __launch_bounds__(256) void k_p1(const float* __restrict__ w1) {
    __shared__ float ws[504];    // [(c*7+j)*12 + co]
    int tid = threadIdx.x, lane = tid & 31, wid = tid >> 5;
    int b = blockIdx.x * 32 + lane;
    for (int i = tid; i < 504; i += 256) { int co = i/42, k = i%42; ws[k*12+co] = w1[i]; }
    __syncthreads();
    int gw = blockIdx.y * 8 + wid;           // 0..31
    for (int t = gw; t < 450; t += 32) {
        int hh = t / 50, ox = t % 50;
        int s = 1 << hh, px = 2*ox;
        float acc0[12], acc1[12];
        #pragma unroll
        for (int u = 0; u < 12; u++) { acc0[u] = 0.f; acc1[u] = 0.f; }
        #pragma unroll
        for (int c = 0; c < 6; c++) {
            #pragma unroll
            for (int j = 0; j < 7; j++) {
                int t0 = px + (j-3)*s;
                float a0 = (t0 >= 0 && t0 < 100) ? g_xT[(t0*6 + c)*NB + b]     : 0.f;
                float a1 = (t0 >= -1 && t0 < 99) ? g_xT[((t0+1)*6 + c)*NB + b] : 0.f;
                const float* wp = &ws[(c*7 + j)*12];
                #pragma unroll
                for (int u = 0; u < 12; u++) { float w = wp[u]; acc0[u] += w*a0; acc1[u] += w*a1; }
            }
        }
        float inv = 1.f/(float)s;
        #pragma unroll
        for (int u = 0; u < 12; u++) {
            float v = fmaxf(fmaxf(acc0[u], acc1[u]), 0.f) * inv;
            g_a1T[(u*450 + t)*NB + b] = v;
        }
    }
}

// ---------------- generic stats: one block per feature row ----------------
__device__ __forceinline__ void stats_body(const float* __restrict__ src, int fpc,
                                           int offS, int offQ) {
    int feat = blockIdx.x;
    int c = feat / fpc;
    const float* p = src + (size_t)feat * NB;
    float s = 0.f, q = 0.f;
    for (int i = threadIdx.x; i < NB; i += 256) { float v = p[i]; s += v; q += v*v; }
    #pragma unroll
    for (int o = 16; o; o >>= 1) {
        s += __shfl_down_sync(0xffffffffu, s, o);
        q += __shfl_down_sync(0xffffffffu, q, o);
    }
    __shared__ float ss[8], qq[8];
    int wid = threadIdx.x >> 5, lane = threadIdx.x & 31;
    if (lane == 0) { ss[wid] = s; qq[wid] = q; }
    __syncthreads();
    if (threadIdx.x == 0) {
        float S = 0.f, Q = 0.f;
        #pragma unroll
        for (int i = 0; i < 8; i++) { S += ss[i]; Q += qq[i]; }
        atomicAdd(&g_stats[offS + c], (double)S);
        atomicAdd(&g_stats[offQ + c], (double)Q);
    }
}
__global__ __launch_bounds__(256) void k_stats1() { stats_body(g_a1T, 450,   0,  12); }
__global__ __launch_bounds__(256) void k_stats2() { stats_body(g_a2T,  84,  24,  48); }
__global__ __launch_bounds__(256) void k_stats3() { stats_body(g_a3T,  15,  72, 120); }
__global__ __launch_bounds__(256) void k_stats4() { stats_body(g_a4T,   3, 168, 264); }

// ---------------- bn+pool passes ----------------
__global__ __launch_bounds__(256) void k_bp1(const float* __restrict__ g1, const float* __restrict__ b1) {
    int f = blockIdx.y;                       // 0..2699
    int c = f/225, rem = f%225, hh = rem/25, xx = rem%25;
    __shared__ float sAB[2];
    if (threadIdx.x == 0) {
        double m = g_stats[c] / 1843200.0;
        double v = g_stats[12+c] / 1843200.0 - m*m;
        float a = g1[c] * rsqrtf((float)v + EPSF);
        sAB[0] = a; sAB[1] = b1[c] - (float)m*a;
    }
    __syncthreads();
    float A = sAB[0], B = sAB[1];
    int b = blockIdx.x*256 + threadIdx.x;
    size_t i0 = (size_t)(c*450 + hh*50 + 2*xx)*NB + b;
    float p0 = g_a1T[i0], p1 = g_a1T[i0 + NB];
    g_p2[(size_t)f*NB + b] = fmaxf(A*p0 + B, A*p1 + B);
}

__global__ __launch_bounds__(256) void k_bp2(const float* __restrict__ g2, const float* __restrict__ b2) {
    int f = blockIdx.y;                       // 0..1007
    int c = f/42, rem = f%42, hh = rem/6, xx = rem%6;
    __shared__ float sAB[2];
    if (threadIdx.x == 0) {
        double m = g_stats[24+c] / 344064.0;
        double v = g_stats[48+c] / 344064.0 - m*m;
        float a = g2[c] * rsqrtf((float)v + EPSF);
        sAB[0] = a; sAB[1] = b2[c] - (float)m*a;
    }
    __syncthreads();
    float A = sAB[0], B = sAB[1];
    int b = blockIdx.x*256 + threadIdx.x;
    size_t i0 = (size_t)(c*84 + hh*12 + 2*xx)*NB + b;
    float p0 = g_a2T[i0], p1 = g_a2T[i0 + NB];
    g_p3[(size_t)f*NB + b] = fmaxf(A*p0 + B, A*p1 + B);
}

__global__ __launch_bounds__(256) void k_bp3(const float* __restrict__ g3, const float* __restrict__ b3) {
    int f = blockIdx.y;                       // 0..719
    int c = f/15;
    __shared__ float sAB[2];
    if (threadIdx.x == 0) {
        double m = g_stats[72+c] / 61440.0;
        double v = g_stats[120+c] / 61440.0 - m*m;
        float a = g3[c] * rsqrtf((float)v + EPSF);
        sAB[0] = a; sAB[1] = b3[c] - (float)m*a;
    }
    __syncthreads();
    int b = blockIdx.x*256 + threadIdx.x;
    g_p4[(size_t)f*NB + b] = sAB[0]*g_a3T[(size_t)f*NB + b] + sAB[1];
}

// ---------------- Phase 2: gg_conv w2, warp=32 samples, 24 co in regs ----------------
__global__ __launch_bounds__(256) void k_p2(const float* __restrict__ w2) {
    __shared__ float ws[4320];  // [(c*15+r*5+j)*24 + co]
    int tid = threadIdx.x, lane = tid & 31, wid = tid >> 5;
    int b = blockIdx.x * 32 + lane;
    for (int i = tid; i < 4320; i += 256) { int co = i/180, k = i%180; ws[k*24+co] = w2[i]; }
    __syncthreads();
    int gw = blockIdx.y * 8 + wid;           // 0..23
    for (int t = gw; t < 84; t += 24) {
        int ii = t / 12, ox = t % 12;
        int s = 1 << ii, px = 2*ox;
        float acc0[24], acc1[24];
        #pragma unroll
        for (int u = 0; u < 24; u++) { acc0[u] = 0.f; acc1[u] = 0.f; }
        for (int c = 0; c < 12; c++) {
            #pragma unroll
            for (int r = 0; r < 3; r++) {
                const float* pb = &g_p2[(size_t)((c*9 + ii + r)*25)*NB + b];
                const float* wkb = &ws[(c*15 + r*5)*24];
                #pragma unroll
                for (int j = 0; j < 5; j++) {
                    int x0 = px + (j-2)*s;
                    float a0 = (x0 >= 0 && x0 < 25) ? pb[(size_t)x0*NB]     : 0.f;
                    float a1 = (x0 >= -1 && x0 < 24) ? pb[(size_t)(x0+1)*NB] : 0.f;
                    const float* wp = wkb + j*24;
                    #pragma unroll
                    for (int u = 0; u < 24; u++) { float w = wp[u]; acc0[u] += w*a0; acc1[u] += w*a1; }
                }
            }
        }
        float inv = 1.f/(float)s;
        #pragma unroll
        for (int u = 0; u < 24; u++) {
            float v = fmaxf(fmaxf(acc0[u], acc1[u]), 0.f) * inv;
            g_a2T[(size_t)(u*84 + t)*NB + b] = v;
        }
    }
}

// ---------------- Phase 3: gg_conv w3, warp=32 samples, 24-of-48 co per block ----------------
__global__ __launch_bounds__(256) void k_p3(const float* __restrict__ w3) {
    __shared__ float ws[8640];  // [(c*15+r*5+j)*24 + u], co = co0+u
    int tid = threadIdx.x, lane = tid & 31, wid = tid >> 5;
    int b = blockIdx.x * 32 + lane;
    int co0 = blockIdx.y * 24;
    for (int i = tid; i < 8640; i += 256) { int u = i/360, k = i%360; ws[k*24+u] = w3[(co0+u)*360 + k]; }
    __syncthreads();
    for (int t = wid; t < 15; t += 8) {
        int ii = t / 3, ox = t % 3;
        int s = 1 << ii, px = 2*ox;
        float acc0[24], acc1[24];
        #pragma unroll
        for (int u = 0; u < 24; u++) { acc0[u] = 0.f; acc1[u] = 0.f; }
        for (int c = 0; c < 24; c++) {
            #pragma unroll
            for (int r = 0; r < 3; r++) {
                const float* pb = &g_p3[(size_t)((c*7 + ii + r)*6)*NB + b];
                const float* wkb = &ws[(c*15 + r*5)*24];
                #pragma unroll
                for (int j = 0; j < 5; j++) {
                    int x0 = px + (j-2)*s;
                    float a0 = (x0 >= 0 && x0 < 6) ? pb[(size_t)x0*NB]      : 0.f;
                    float a1 = (x0 >= -1 && x0 < 5) ? pb[(size_t)(x0+1)*NB] : 0.f;
                    const float* wp = wkb + j*24;
                    #pragma unroll
                    for (int u = 0; u < 24; u++) { float w = wp[u]; acc0[u] += w*a0; acc1[u] += w*a1; }
                }
            }
        }
        float inv = 1.f/(float)s;
        #pragma unroll
        for (int u = 0; u < 24; u++) {
            float v = fmaxf(fmaxf(acc0[u], acc1[u]), 0.f) * inv;
            g_a3T[(size_t)((co0+u)*15 + t)*NB + b] = v;
        }
    }
}

// ---------------- Phase 4: gg_conv w4, warp=32 samples, warp owns a 12-co group ----------------
__global__ __launch_bounds__(256) void k_p4(const float* __restrict__ w4) {
    extern __shared__ float ws4[];  // 41472: [(c*9+r*3+j)*96 + co]
    int tid = threadIdx.x, lane = tid & 31, wid = tid >> 5;
    int b = blockIdx.x * 32 + lane;
    for (int i = tid; i < 41472; i += 256) { int co = i/432, k = i%432; ws4[k*96+co] = w4[i]; }
    __syncthreads();
    // 24 tasks = ii(3) x cog(8); warp w -> cog=w, ii=0..2
    for (int t = wid; t < 24; t += 8) {
        int ii = t / 8, cog = t % 8;
        int co0 = cog * 12;
        int s = 1 << ii;
        float acc0[12], acc1[12];
        #pragma unroll
        for (int u = 0; u < 12; u++) { acc0[u] = 0.f; acc1[u] = 0.f; }
        for (int c = 0; c < 48; c++) {
            #pragma unroll
            for (int r = 0; r < 3; r++) {
                const float* pb = &g_p4[(size_t)((c*5 + ii + r)*3)*NB + b];
                const float* wkb = &ws4[(c*9 + r*3)*96 + co0];
                #pragma unroll
                for (int j = 0; j < 3; j++) {
                    int x0 = (j-1)*s;
                    float a0 = (x0 >= 0 && x0 < 3) ? pb[(size_t)x0*NB]      : 0.f;
                    float a1 = (x0 >= -1 && x0 < 2) ? pb[(size_t)(x0+1)*NB] : 0.f;
                    const float* wp = wkb + j*96;
                    #pragma unroll
                    for (int u = 0; u < 12; u++) { float w = wp[u]; acc0[u] += w*a0; acc1[u] += w*a1; }
                }
            }
        }
        float inv = 1.f/(float)s;
        #pragma unroll
        for (int u = 0; u < 12; u++) {
            float v = fmaxf(fmaxf(acc0[u], acc1[u]), 0.f) * inv;
            g_a4T[(size_t)((co0+u)*3 + ii)*NB + b] = v;
        }
    }
}

// ---------------- Phase 5a: bn4 affine + collapse 3 FCs into (6x288) + bias ----------------
__global__ __launch_bounds__(256) void k_phase5a(const float* __restrict__ g4, const float* __restrict__ b4,
                                                 const float* __restrict__ f1w, const float* __restrict__ f1b,
                                                 const float* __restrict__ f2w, const float* __restrict__ f2b,
                                                 const float* __restrict__ f3w, const float* __restrict__ f3b) {
    __shared__ float A4[96], B4[96], W23[576], bcs[6];
    int tid = threadIdx.x;
    if (tid < 96) {
        double m = g_stats[168+tid] / 12288.0;
        double v = g_stats[264+tid] / 12288.0 - m*m;
        float a = g4[tid] * rsqrtf((float)v + EPSF);
        A4[tid] = a; B4[tid] = b4[tid] - (float)m*a;
    }
    if (tid < 6) bcs[tid] = 0.f;
    for (int idx = tid; idx < 576; idx += 256) {
        int j = idx / 96, k = idx % 96;
        float s = 0.f;
        for (int l = 0; l < 48; l++) s += f3w[j*48 + l] * f2w[l*96 + k];
        W23[idx] = s;
    }
    __syncthreads();
    for (int idx = tid; idx < 1728; idx += 256) {
        int j = idx / 288, i = idx % 288;
        int c = i / 3;
        float s0 = 0.f;
        for (int k = 0; k < 96; k++) s0 += W23[j*96 + k] * f1w[k*288 + i];
        g_Wc[idx] = s0 * A4[c];
        atomicAdd(&bcs[j], s0 * B4[c]);
    }
    __syncthreads();
    if (tid < 6) {
        int j = tid;
        float bb = f3b[j];
        for (int l = 0; l < 48; l++) bb += f3w[j*48 + l] * f2b[l];
        for (int k = 0; k < 96; k++) bb += W23[j*96 + k] * f1b[k];
        g_bc[j] = bcs[j] + bb;
    }
}

// ---------------- Phase 5b: out[b][6] from a4T planes ----------------
__global__ __launch_bounds__(256) void k_phase5b(float* __restrict__ out) {
    __shared__ float Wcs[1728];
    for (int i = threadIdx.x; i < 1728; i += 256) Wcs[i] = g_Wc[i];
    __syncthreads();
    int b = blockIdx.x*256 + threadIdx.x;
    float acc[6] = {0.f,0.f,0.f,0.f,0.f,0.f};
    for (int f = 0; f < 288; f++) {
        float v = g_a4T[(size_t)f*NB + b];
        #pragma unroll
        for (int j = 0; j < 6; j++) acc[j] += v * Wcs[j*288 + f];
    }
    #pragma unroll
    for (int j = 0; j < 6; j++) out[b*6 + j] = acc[j] + g_bc[j];
}

// ---------------- launcher ----------------
extern "C" void kernel_launch(void* const* d_in, const int* in_sizes, int n_in,
                              void* d_out, int out_size) {
    const float* x   = (const float*)d_in[0];
    const float* w1  = (const float*)d_in[1];
    const float* w2  = (const float*)d_in[2];
    const float* w3  = (const float*)d_in[3];
    const float* w4  = (const float*)d_in[4];
    const float* g1  = (const float*)d_in[5];
    const float* b1  = (const float*)d_in[6];
    const float* g2  = (const float*)d_in[7];
    const float* b2  = (const float*)d_in[8];
    const float* g3  = (const float*)d_in[9];
    const float* b3  = (const float*)d_in[10];
    const float* g4  = (const float*)d_in[11];
    const float* b4  = (const float*)d_in[12];
    const float* f1w = (const float*)d_in[13];
    const float* f1b = (const float*)d_in[14];
    const float* f2w = (const float*)d_in[15];
    const float* f2b = (const float*)d_in[16];
    const float* f3w = (const float*)d_in[17];
    const float* f3b = (const float*)d_in[18];
    float* out = (float*)d_out;

    static const int SM4 = 41472 * 4;
    cudaFuncSetAttribute(k_p4, cudaFuncAttributeMaxDynamicSharedMemorySize, SM4);

    k_zero<<<1, 384>>>();
    k_tr<<<dim3(128, 19), dim3(32, 8)>>>(x);
    k_p1<<<dim3(128, 4), 256>>>(w1);
    k_stats1<<<5400, 256>>>();
    k_bp1<<<dim3(16, 2700), 256>>>(g1, b1);
    k_p2<<<dim3(128, 3), 256>>>(w2);
    k_stats2<<<2016, 256>>>();
    k_bp2<<<dim3(16, 1008), 256>>>(g2, b2);
    k_p3<<<dim3(128, 2), 256>>>(w3);
    k_stats3<<<720, 256>>>();
    k_bp3<<<dim3(16, 720), 256>>>(g3, b3);
    k_p4<<<128, 256, SM4>>>(w4);
    k_stats4<<<288, 256>>>();
    k_phase5a<<<1, 256>>>(g4, b4, f1w, f1b, f2w, f2b, f3w, f3b);
    k_phase5b<<<16, 256>>>(out);
}

// round 4
// speedup vs baseline: 4.5679x; 1.1626x over previous
#include <cuda_runtime.h>

#define EPSF 2e-5f
#define NB 4096

typedef unsigned long long u64;

__device__ __forceinline__ u64 ld2(const float* p) {
    return *reinterpret_cast<const u64*>(p);
}
__device__ __forceinline__ u64 fma2(u64 a, u64 b, u64 c) {
    u64 d;
    asm("fma.rn.f32x2 %0, %1, %2, %3;" : "=l"(d) : "l"(a), "l"(b), "l"(c));
    return d;
}
__device__ __forceinline__ float2 up2(u64 v) {
    float2 r;
    asm("mov.b64 {%0,%1}, %2;" : "=f"(r.x), "=f"(r.y) : "l"(v));
    return r;
}
__device__ __forceinline__ u64 dupw(float w) {
    u64 d;
    asm("mov.b64 %0, {%1,%1};" : "=l"(d) : "f"(w));
    return d;
}

// ---------------- scratch planes, [feature][batch], 16B aligned ----------------
__device__ __align__(16) float  g_xT [600*NB];
__device__ __align__(16) float  g_a1T[5400*NB];
__device__ __align__(16) float  g_p2 [2700*NB];
__device__ __align__(16) float  g_a2T[2016*NB];
__device__ __align__(16) float  g_p3 [1008*NB];
__device__ __align__(16) float  g_a3T[720*NB];
__device__ __align__(16) float  g_p4 [720*NB];
__device__ __align__(16) float  g_a4T[288*NB];
__device__ double g_stats[360];   // s1:0 q1:12 s2:24 q2:48 s3:72 q3:120 s4:168 q4:264
__device__ float  g_Wc[6*288];
__device__ float  g_bc[6];

__global__ void k_zero() {
    int t = threadIdx.x;
    if (t < 360) g_stats[t] = 0.0;
}

// ---------------- transpose x (4096,600) -> xT (600,4096) ----------------
__global__ void k_tr(const float* __restrict__ x) {
    __shared__ float tile[32][33];
    int bx = blockIdx.x * 32;
    int fy = blockIdx.y * 32;
    int tx = threadIdx.x, ty = threadIdx.y;
    #pragma unroll
    for (int m = 0; m < 4; m++) {
        int ff = fy + tx;
        tile[ty + m*8][tx] = (ff < 600) ? x[(bx + ty + m*8)*600 + ff] : 0.f;
    }
    __syncthreads();
    #pragma unroll
    for (int m = 0; m < 4; m++) {
        int ff = fy + ty + m*8;
        if (ff < 600) g_xT[ff*NB + bx + tx] = tile[tx][ty + m*8];
    }
}

// ---------------- Phase 1: lift conv (packed x2 samples) + fused stats ----------------
__global__ __launch_bounds__(256) void k_p1(const float* __restrict__ w1) {
    __shared__ u64 wd[504];           // [(c*7+j)*12 + co] duplicated
    __shared__ float ssum[12], ssq[12];
    int tid = threadIdx.x, lane = tid & 31, wid = tid >> 5;
    int b = blockIdx.x * 64 + lane * 2;
    for (int i = tid; i < 504; i += 256) { int co = i/42, k = i%42; wd[k*12+co] = dupw(w1[i]); }
    if (tid < 12) { ssum[tid] = 0.f; ssq[tid] = 0.f; }
    __syncthreads();
    float s[12], q[12];
    #pragma unroll
    for (int u = 0; u < 12; u++) { s[u] = 0.f; q[u] = 0.f; }
    int gw = blockIdx.y * 8 + wid;    // 0..63
    for (int t = gw; t < 450; t += 64) {
        int hh = t / 50, ox = t % 50;
        int sc = 1 << hh, px = 2*ox;
        u64 acc0[12], acc1[12];
        #pragma unroll
        for (int u = 0; u < 12; u++) { acc0[u] = 0ull; acc1[u] = 0ull; }
        #pragma unroll
        for (int c = 0; c < 6; c++) {
            #pragma unroll
            for (int j = 0; j < 7; j++) {
                int t0 = px + (j-3)*sc;
                u64 a0 = (t0 >= 0 && t0 < 100) ? ld2(&g_xT[(size_t)(t0*6 + c)*NB + b])     : 0ull;
                u64 a1 = (t0 >= -1 && t0 < 99) ? ld2(&g_xT[(size_t)((t0+1)*6 + c)*NB + b]) : 0ull;
                const u64* wp = &wd[(c*7 + j)*12];
                #pragma unroll
                for (int u = 0; u < 12; u++) {
                    u64 w = wp[u];
                    acc0[u] = fma2(w, a0, acc0[u]);
                    acc1[u] = fma2(w, a1, acc1[u]);
                }
            }
        }
        float inv = 1.f/(float)sc;
        #pragma unroll
        for (int u = 0; u < 12; u++) {
            float2 x0 = up2(acc0[u]), x1 = up2(acc1[u]);
            float vx = fmaxf(fmaxf(x0.x, x1.x), 0.f) * inv;
            float vy = fmaxf(fmaxf(x0.y, x1.y), 0.f) * inv;
            *reinterpret_cast<float2*>(&g_a1T[(size_t)(u*450 + t)*NB + b]) = make_float2(vx, vy);
            s[u] += vx + vy;
            q[u] += vx*vx + vy*vy;
        }
    }
    #pragma unroll
    for (int u = 0; u < 12; u++) {
        #pragma unroll
        for (int o = 16; o; o >>= 1) {
            s[u] += __shfl_down_sync(0xffffffffu, s[u], o);
            q[u] += __shfl_down_sync(0xffffffffu, q[u], o);
        }
    }
    if (lane == 0) {
        #pragma unroll
        for (int u = 0; u < 12; u++) { atomicAdd(&ssum[u], s[u]); atomicAdd(&ssq[u], q[u]); }
    }
    __syncthreads();
    if (tid < 12) {
        atomicAdd(&g_stats[tid],    (double)ssum[tid]);
        atomicAdd(&g_stats[12+tid], (double)ssq[tid]);
    }
}

// ---------------- bn+pool passes, float4 ----------------
__global__ __launch_bounds__(256) void k_bp1(const float* __restrict__ g1, const float* __restrict__ b1) {
    int f = blockIdx.y;                       // 0..2699
    int c = f/225, rem = f%225, hh = rem/25, xx = rem%25;
    __shared__ float sAB[2];
    if (threadIdx.x == 0) {
        double m = g_stats[c] / 1843200.0;
        double v = g_stats[12+c] / 1843200.0 - m*m;
        float a = g1[c] * rsqrtf((float)v + EPSF);
        sAB[0] = a; sAB[1] = b1[c] - (float)m*a;
    }
    __syncthreads();
    float A = sAB[0], B = sAB[1];
    int b = (blockIdx.x*256 + threadIdx.x)*4;
    size_t i0 = (size_t)(c*450 + hh*50 + 2*xx)*NB + b;
    float4 p0 = *reinterpret_cast<const float4*>(&g_a1T[i0]);
    float4 p1 = *reinterpret_cast<const float4*>(&g_a1T[i0 + NB]);
    float4 o;
    o.x = fmaxf(fmaf(A,p0.x,B), fmaf(A,p1.x,B));
    o.y = fmaxf(fmaf(A,p0.y,B), fmaf(A,p1.y,B));
    o.z = fmaxf(fmaf(A,p0.z,B), fmaf(A,p1.z,B));
    o.w = fmaxf(fmaf(A,p0.w,B), fmaf(A,p1.w,B));
    *reinterpret_cast<float4*>(&g_p2[(size_t)f*NB + b]) = o;
}

__global__ __launch_bounds__(256) void k_bp2(const float* __restrict__ g2, const float* __restrict__ b2) {
    int f = blockIdx.y;                       // 0..1007
    int c = f/42, rem = f%42, hh = rem/6, xx = rem%6;
    __shared__ float sAB[2];
    if (threadIdx.x == 0) {
        double m = g_stats[24+c] / 344064.0;
        double v = g_stats[48+c] / 344064.0 - m*m;
        float a = g2[c] * rsqrtf((float)v + EPSF);
        sAB[0] = a; sAB[1] = b2[c] - (float)m*a;
    }
    __syncthreads();
    float A = sAB[0], B = sAB[1];
    int b = (blockIdx.x*256 + threadIdx.x)*4;
    size_t i0 = (size_t)(c*84 + hh*12 + 2*xx)*NB + b;
    float4 p0 = *reinterpret_cast<const float4*>(&g_a2T[i0]);
    float4 p1 = *reinterpret_cast<const float4*>(&g_a2T[i0 + NB]);
    float4 o;
    o.x = fmaxf(fmaf(A,p0.x,B), fmaf(A,p1.x,B));
    o.y = fmaxf(fmaf(A,p0.y,B), fmaf(A,p1.y,B));
    o.z = fmaxf(fmaf(A,p0.z,B), fmaf(A,p1.z,B));
    o.w = fmaxf(fmaf(A,p0.w,B), fmaf(A,p1.w,B));
    *reinterpret_cast<float4*>(&g_p3[(size_t)f*NB + b]) = o;
}

__global__ __launch_bounds__(256) void k_bp3(const float* __restrict__ g3, const float* __restrict__ b3) {
    int f = blockIdx.y;                       // 0..719
    int c = f/15;
    __shared__ float sAB[2];
    if (threadIdx.x == 0) {
        double m = g_stats[72+c] / 61440.0;
        double v = g_stats[120+c] / 61440.0 - m*m;
        float a = g3[c] * rsqrtf((float)v + EPSF);
        sAB[0] = a; sAB[1] = b3[c] - (float)m*a;
    }
    __syncthreads();
    float A = sAB[0], B = sAB[1];
    int b = (blockIdx.x*256 + threadIdx.x)*4;
    size_t i0 = (size_t)f*NB + b;
    float4 p = *reinterpret_cast<const float4*>(&g_a3T[i0]);
    float4 o;
    o.x = fmaf(A,p.x,B); o.y = fmaf(A,p.y,B); o.z = fmaf(A,p.z,B); o.w = fmaf(A,p.w,B);
    *reinterpret_cast<float4*>(&g_p4[i0]) = o;
}

// ---------------- Phase 2: gg_conv w2 (packed) + fused stats ----------------
// tasks 0..167: cog = task&1 (12 cos), pos = task>>1 (ii*12+ox). Warp parity fixed.
__global__ __launch_bounds__(256) void k_p2(const float* __restrict__ w2) {
    __shared__ u64 wd[4320];          // [(c*15+r*5+j)*24 + co] duplicated
    __shared__ float ssum[24], ssq[24];
    int tid = threadIdx.x, lane = tid & 31, wid = tid >> 5;
    int b = blockIdx.x * 64 + lane * 2;
    for (int i = tid; i < 4320; i += 256) { int co = i/180, k = i%180; wd[k*24+co] = dupw(w2[i]); }
    if (tid < 24) { ssum[tid] = 0.f; ssq[tid] = 0.f; }
    __syncthreads();
    int gw = blockIdx.y * 8 + wid;    // 0..55
    int cog = gw & 1;
    int co0 = cog * 12;
    float s[12], q[12];
    #pragma unroll
    for (int u = 0; u < 12; u++) { s[u] = 0.f; q[u] = 0.f; }
    for (int task = gw; task < 168; task += 56) {
        int pos = task >> 1;
        int ii = pos / 12, ox = pos % 12;
        int sc = 1 << ii, px = 2*ox;
        u64 acc0[12], acc1[12];
        #pragma unroll
        for (int u = 0; u < 12; u++) { acc0[u] = 0ull; acc1[u] = 0ull; }
        for (int c = 0; c < 12; c++) {
            #pragma unroll
            for (int r = 0; r < 3; r++) {
                const float* pb = &g_p2[(size_t)((c*9 + ii + r)*25)*NB + b];
                const u64* wk = &wd[(c*15 + r*5)*24 + co0];
                #pragma unroll
                for (int j = 0; j < 5; j++) {
                    int x0 = px + (j-2)*sc;
                    u64 a0 = (x0 >= 0 && x0 < 25) ? ld2(pb + (size_t)x0*NB)      : 0ull;
                    u64 a1 = (x0 >= -1 && x0 < 24) ? ld2(pb + (size_t)(x0+1)*NB) : 0ull;
                    const u64* wp = wk + j*24;
                    #pragma unroll
                    for (int u = 0; u < 12; u++) {
                        u64 w = wp[u];
                        acc0[u] = fma2(w, a0, acc0[u]);
                        acc1[u] = fma2(w, a1, acc1[u]);
                    }
                }
            }
        }
        float inv = 1.f/(float)sc;
        #pragma unroll
        for (int u = 0; u < 12; u++) {
            float2 x0 = up2(acc0[u]), x1 = up2(acc1[u]);
            float vx = fmaxf(fmaxf(x0.x, x1.x), 0.f) * inv;
            float vy = fmaxf(fmaxf(x0.y, x1.y), 0.f) * inv;
            *reinterpret_cast<float2*>(&g_a2T[(size_t)((co0+u)*84 + pos)*NB + b]) = make_float2(vx, vy);
            s[u] += vx + vy;
            q[u] += vx*vx + vy*vy;
        }
    }
    #pragma unroll
    for (int u = 0; u < 12; u++) {
        #pragma unroll
        for (int o = 16; o; o >>= 1) {
            s[u] += __shfl_down_sync(0xffffffffu, s[u], o);
            q[u] += __shfl_down_sync(0xffffffffu, q[u], o);
        }
    }
    if (lane == 0) {
        #pragma unroll
        for (int u = 0; u < 12; u++) { atomicAdd(&ssum[co0+u], s[u]); atomicAdd(&ssq[co0+u], q[u]); }
    }
    __syncthreads();
    if (tid < 24) {
        atomicAdd(&g_stats[24+tid], (double)ssum[tid]);
        atomicAdd(&g_stats[48+tid], (double)ssq[tid]);
    }
}

// ---------------- Phase 3: gg_conv w3 (packed) + fused stats ----------------
// blockIdx.y: bit1 = half (24-of-48 cos), bit0 = task group.
// tasks 0..29: cog = task&1, pos = task>>1.
__global__ __launch_bounds__(256) void k_p3(const float* __restrict__ w3) {
    extern __shared__ u64 dyn3[];
    u64* wd = dyn3;                         // 8640: [(c*15+r*5+j)*24 + u]
    float* ssum = (float*)(dyn3 + 8640);    // 24
    float* ssq  = ssum + 24;                // 24
    int tid = threadIdx.x, lane = tid & 31, wid = tid >> 5;
    int b = blockIdx.x * 64 + lane * 2;
    int half = blockIdx.y >> 1;
    int tg   = blockIdx.y & 1;
    int cbase = half * 24;
    for (int i = tid; i < 8640; i += 256) {
        int u = i/360, k = i%360;
        wd[k*24+u] = dupw(w3[(cbase+u)*360 + k]);
    }
    if (tid < 24) { ssum[tid] = 0.f; ssq[tid] = 0.f; }
    __syncthreads();
    int gw = tg * 8 + wid;    // 0..15
    int cog = gw & 1;
    int co0 = cog * 12;
    float s[12], q[12];
    #pragma unroll
    for (int u = 0; u < 12; u++) { s[u] = 0.f; q[u] = 0.f; }
    for (int task = gw; task < 30; task += 16) {
        int pos = task >> 1;   // 0..14
        int ii = pos / 3, ox = pos % 3;
        int sc = 1 << ii, px = 2*ox;
        u64 acc0[12], acc1[12];
        #pragma unroll
        for (int u = 0; u < 12; u++) { acc0[u] = 0ull; acc1[u] = 0ull; }
        for (int c = 0; c < 24; c++) {
            #pragma unroll
            for (int r = 0; r < 3; r++) {
                const float* pb = &g_p3[(size_t)((c*7 + ii + r)*6)*NB + b];
                const u64* wk = &wd[(c*15 + r*5)*24 + co0];
                #pragma unroll
                for (int j = 0; j < 5; j++) {
                    int x0 = px + (j-2)*sc;
                    u64 a0 = (x0 >= 0 && x0 < 6) ? ld2(pb + (size_t)x0*NB)      : 0ull;
                    u64 a1 = (x0 >= -1 && x0 < 5) ? ld2(pb + (size_t)(x0+1)*NB) : 0ull;
                    const u64* wp = wk + j*24;
                    #pragma unroll
                    for (int u = 0; u < 12; u++) {
                        u64 w = wp[u];
                        acc0[u] = fma2(w, a0, acc0[u]);
                        acc1[u] = fma2(w, a1, acc1[u]);
                    }
                }
            }
        }
        float inv = 1.f/(float)sc;
        #pragma unroll
        for (int u = 0; u < 12; u++) {
            float2 x0 = up2(acc0[u]), x1 = up2(acc1[u]);
            float vx = fmaxf(fmaxf(x0.x, x1.x), 0.f) * inv;
            float vy = fmaxf(fmaxf(x0.y, x1.y), 0.f) * inv;
            *reinterpret_cast<float2*>(&g_a3T[(size_t)((cbase+co0+u)*15 + pos)*NB + b]) = make_float2(vx, vy);
            s[u] += vx + vy;
            q[u] += vx*vx + vy*vy;
        }
    }
    #pragma unroll
    for (int u = 0; u < 12; u++) {
        #pragma unroll
        for (int o = 16; o; o >>= 1) {
            s[u] += __shfl_down_sync(0xffffffffu, s[u], o);
            q[u] += __shfl_down_sync(0xffffffffu, q[u], o);
        }
    }
    if (lane == 0) {
        #pragma unroll
        for (int u = 0; u < 12; u++) { atomicAdd(&ssum[co0+u], s[u]); atomicAdd(&ssq[co0+u], q[u]); }
    }
    __syncthreads();
    if (tid < 24) {
        atomicAdd(&g_stats[72+cbase+tid],  (double)ssum[tid]);
        atomicAdd(&g_stats[120+cbase+tid], (double)ssq[tid]);
    }
}

// ---------------- Phase 4: gg_conv w4 (packed) + fused stats ----------------
// blockIdx.y in 0..3: 24 cos each. 6 warps: task = cog(2) x ii(3).
__global__ __launch_bounds__(192) void k_p4(const float* __restrict__ w4) {
    extern __shared__ u64 dyn4[];
    u64* wd = dyn4;                          // 10368: [(c*9+r*3+j)*24 + u]
    float* ssum = (float*)(dyn4 + 10368);    // 24
    float* ssq  = ssum + 24;                 // 24
    int tid = threadIdx.x, lane = tid & 31, wid = tid >> 5;
    int b = blockIdx.x * 64 + lane * 2;
    int cbase = blockIdx.y * 24;
    for (int i = tid; i < 10368; i += 192) {
        int u = i/432, k = i%432;
        wd[k*24+u] = dupw(w4[(cbase+u)*432 + k]);
    }
    if (tid < 24) { ssum[tid] = 0.f; ssq[tid] = 0.f; }
    __syncthreads();
    // warp wid in 0..5: cog = wid/3, ii = wid%3
    int cog = wid / 3;
    int ii  = wid % 3;
    int co0 = cog * 12;
    int sc = 1 << ii;
    u64 acc0[12], acc1[12];
    #pragma unroll
    for (int u = 0; u < 12; u++) { acc0[u] = 0ull; acc1[u] = 0ull; }
    for (int c = 0; c < 48; c++) {
        #pragma unroll
        for (int r = 0; r < 3; r++) {
            const float* pb = &g_p4[(size_t)((c*5 + ii + r)*3)*NB + b];
            const u64* wk = &wd[(c*9 + r*3)*24 + co0];
            #pragma unroll
            for (int j = 0; j < 3; j++) {
                int x0 = (j-1)*sc;
                u64 a0 = (x0 >= 0 && x0 < 3) ? ld2(pb + (size_t)x0*NB)      : 0ull;
                u64 a1 = (x0 >= -1 && x0 < 2) ? ld2(pb + (size_t)(x0+1)*NB) : 0ull;
                const u64* wp = wk + j*24;
                #pragma unroll
                for (int u = 0; u < 12; u++) {
                    u64 w = wp[u];
                    acc0[u] = fma2(w, a0, acc0[u]);
                    acc1[u] = fma2(w, a1, acc1[u]);
                }
            }
        }
    }
    float s[12], q[12];
    float inv = 1.f/(float)sc;
    #pragma unroll
    for (int u = 0; u < 12; u++) {
        float2 x0 = up2(acc0[u]), x1 = up2(acc1[u]);
        float vx = fmaxf(fmaxf(x0.x, x1.x), 0.f) * inv;
        float vy = fmaxf(fmaxf(x0.y, x1.y), 0.f) * inv;
        *reinterpret_cast<float2*>(&g_a4T[(size_t)((cbase+co0+u)*3 + ii)*NB + b]) = make_float2(vx, vy);
        s[u] = vx + vy;
        q[u] = vx*vx + vy*vy;
    }
    #pragma unroll
    for (int u = 0; u < 12; u++) {
        #pragma unroll
        for (int o = 16; o; o >>= 1) {
            s[u] += __shfl_down_sync(0xffffffffu, s[u], o);
            q[u] += __shfl_down_sync(0xffffffffu, q[u], o);
        }
    }
    if (lane == 0) {
        #pragma unroll
        for (int u = 0; u < 12; u++) { atomicAdd(&ssum[co0+u], s[u]); atomicAdd(&ssq[co0+u], q[u]); }
    }
    __syncthreads();
    if (tid < 24) {
        atomicAdd(&g_stats[168+cbase+tid], (double)ssum[tid]);
        atomicAdd(&g_stats[264+cbase+tid], (double)ssq[tid]);
    }
}

// ---------------- Phase 5a: bn4 affine + collapse 3 FCs into (6x288) + bias ----------------
__global__ __launch_bounds__(256) void k_phase5a(const float* __restrict__ g4, const float* __restrict__ b4,
                                                 const float* __restrict__ f1w, const float* __restrict__ f1b,
                                                 const float* __restrict__ f2w, const float* __restrict__ f2b,
                                                 const float* __restrict__ f3w, const float* __restrict__ f3b) {
    __shared__ float A4[96], B4[96], W23[576], bcs[6];
    int tid = threadIdx.x;
    if (tid < 96) {
        double m = g_stats[168+tid] / 12288.0;
        double v = g_stats[264+tid] / 12288.0 - m*m;
        float a = g4[tid] * rsqrtf((float)v + EPSF);
        A4[tid] = a; B4[tid] = b4[tid] - (float)m*a;
    }
    if (tid < 6) bcs[tid] = 0.f;
    for (int idx = tid; idx < 576; idx += 256) {
        int j = idx / 96, k = idx % 96;
        float s = 0.f;
        for (int l = 0; l < 48; l++) s += f3w[j*48 + l] * f2w[l*96 + k];
        W23[idx] = s;
    }
    __syncthreads();
    for (int idx = tid; idx < 1728; idx += 256) {
        int j = idx / 288, i = idx % 288;
        int c = i / 3;
        float s0 = 0.f;
        for (int k = 0; k < 96; k++) s0 += W23[j*96 + k] * f1w[k*288 + i];
        g_Wc[idx] = s0 * A4[c];
        atomicAdd(&bcs[j], s0 * B4[c]);
    }
    __syncthreads();
    if (tid < 6) {
        int j = tid;
        float bb = f3b[j];
        for (int l = 0; l < 48; l++) bb += f3w[j*48 + l] * f2b[l];
        for (int k = 0; k < 96; k++) bb += W23[j*96 + k] * f1b[k];
        g_bc[j] = bcs[j] + bb;
    }
}

// ---------------- Phase 5b: out[b][6] from a4T planes, 4 samples/thread ----------------
__global__ __launch_bounds__(256) void k_phase5b(float* __restrict__ out) {
    __shared__ float Wcs[1728];
    for (int i = threadIdx.x; i < 1728; i += 256) Wcs[i] = g_Wc[i];
    __syncthreads();
    int b = (blockIdx.x*256 + threadIdx.x)*4;
    float acc[6][4];
    #pragma unroll
    for (int j = 0; j < 6; j++)
        #pragma unroll
        for (int m = 0; m < 4; m++) acc[j][m] = g_bc[j];
    for (int f = 0; f < 288; f++) {
        float4 v = *reinterpret_cast<const float4*>(&g_a4T[(size_t)f*NB + b]);
        #pragma unroll
        for (int j = 0; j < 6; j++) {
            float w = Wcs[j*288 + f];
            acc[j][0] += v.x*w; acc[j][1] += v.y*w; acc[j][2] += v.z*w; acc[j][3] += v.w*w;
        }
    }
    #pragma unroll
    for (int m = 0; m < 4; m++)
        #pragma unroll
        for (int j = 0; j < 6; j++)
            out[(b+m)*6 + j] = acc[j][m];
}

// ---------------- launcher ----------------
extern "C" void kernel_launch(void* const* d_in, const int* in_sizes, int n_in,
                              void* d_out, int out_size) {
    const float* x   = (const float*)d_in[0];
    const float* w1  = (const float*)d_in[1];
    const float* w2  = (const float*)d_in[2];
    const float* w3  = (const float*)d_in[3];
    const float* w4  = (const float*)d_in[4];
    const float* g1  = (const float*)d_in[5];
    const float* b1  = (const float*)d_in[6];
    const float* g2  = (const float*)d_in[7];
    const float* b2  = (const float*)d_in[8];
    const float* g3  = (const float*)d_in[9];
    const float* b3  = (const float*)d_in[10];
    const float* g4  = (const float*)d_in[11];
    const float* b4  = (const float*)d_in[12];
    const float* f1w = (const float*)d_in[13];
    const float* f1b = (const float*)d_in[14];
    const float* f2w = (const float*)d_in[15];
    const float* f2b = (const float*)d_in[16];
    const float* f3w = (const float*)d_in[17];
    const float* f3b = (const float*)d_in[18];
    float* out = (float*)d_out;

    static const int SM3 = 8640*8 + 48*4;
    static const int SM4 = 10368*8 + 48*4;
    cudaFuncSetAttribute(k_p3, cudaFuncAttributeMaxDynamicSharedMemorySize, SM3);
    cudaFuncSetAttribute(k_p4, cudaFuncAttributeMaxDynamicSharedMemorySize, SM4);

    k_zero<<<1, 384>>>();
    k_tr<<<dim3(128, 19), dim3(32, 8)>>>(x);
    k_p1<<<dim3(64, 8), 256>>>(w1);
    k_bp1<<<dim3(4, 2700), 256>>>(g1, b1);
    k_p2<<<dim3(64, 7), 256>>>(w2);
    k_bp2<<<dim3(4, 1008), 256>>>(g2, b2);
    k_p3<<<dim3(64, 4), 256, SM3>>>(w3);
    k_bp3<<<dim3(4, 720), 256>>>(g3, b3);
    k_p4<<<dim3(64, 4), 192, SM4>>>(w4);
    k_phase5a<<<1, 256>>>(g4, b4, f1w, f1b, f2w, f2b, f3w, f3b);
    k_phase5b<<<4, 256>>>(out);
}